// round 17
// baseline (speedup 1.0000x reference)
#include <cuda_runtime.h>
#include <cuda_bf16.h>
#include <math.h>
#include <stdint.h>

// Problem constants
#define NK    8192
#define DD    256
#define NTOK  32768
#define HWSZ  4096
#define ZELEMS 8388608

// Output layout offsets (float32, reference return order)
#define OFF_ZST  0
#define OFF_IDX  8388608
#define OFF_ZQ   8421376
#define OFF_EMB  16809984
#define OFF_CS   18907136
#define OFF_AVG  18915328

#define NSLICE 8
#define KSLICE 1024
#define NTILE32 1024      // NTOK / 32  (int8 coarse: 32-token tiles)
#define RSLICE 16
#define RKS    512
#define SBQ    16256.0f

// Scratch (__device__ globals)
__device__ float g_Ahi[NTOK * DD];
__device__ float g_Alo[NTOK * DD];
__device__ float g_Bhi[NK * DD];
__device__ float g_Blo[NK * DD];
__device__ __align__(16) char g_A1[NTOK * DD];
__device__ __align__(16) char g_A2[NTOK * DD];
__device__ __align__(16) char g_B1[NK * DD];
__device__ __align__(16) char g_B2[NK * DD];
__device__ float g_sA[NTOK];     // per-token quant scale
__device__ float g_nA[NTOK];     // ||a||
__device__ float g_nA2[NTOK];    // ||a2 digits||
__device__ int   g_maxB2Bits;    // max over codes ||b2 digits||
__device__ float2 g_pv[NTILE32 * NSLICE * 32];
__device__ int    g_pi[NTILE32 * NSLICE * 32];
__device__ int   g_flagCnt;
__device__ int   g_flagTok[NTOK];
__device__ float g_rv[NTOK * RSLICE];
__device__ int   g_ri[NTOK * RSLICE];
__device__ int   g_idx[NTOK];
__device__ float g_zqT[NTOK * DD];

// ============================================================================
// helpers
// ============================================================================
__device__ __forceinline__ uint32_t smem_to_u32(const void* p) {
    uint32_t a;
    asm("{ .reg .u64 t; cvta.to.shared.u64 t, %1; cvt.u32.u64 %0, t; }" : "=r"(a) : "l"(p));
    return a;
}
__device__ __forceinline__ void cpasync16(uint32_t dst, const void* src) {
    asm volatile("cp.async.cg.shared.global [%0], [%1], 16;" :: "r"(dst), "l"(src));
}
#define CPASYNC_COMMIT() asm volatile("cp.async.commit_group;" ::: "memory")
#define CPASYNC_WAIT(n)  asm volatile("cp.async.wait_group %0;" :: "n"(n) : "memory")

__device__ __forceinline__ float tf32_rna(float x) {
    uint32_t u;
    asm("cvt.rna.tf32.f32 %0, %1;" : "=r"(u) : "f"(x));
    return __uint_as_float(u);
}

// tf32 m16n8k8 (rescore)
__device__ __forceinline__ void mma8(float* c, const float* a, const float* b) {
    asm volatile(
        "mma.sync.aligned.m16n8k8.row.col.f32.tf32.tf32.f32 "
        "{%0,%1,%2,%3}, {%4,%5,%6,%7}, {%8,%9}, {%0,%1,%2,%3};"
        : "+f"(c[0]), "+f"(c[1]), "+f"(c[2]), "+f"(c[3])
        : "r"(__float_as_uint(a[0])), "r"(__float_as_uint(a[1])),
          "r"(__float_as_uint(a[2])), "r"(__float_as_uint(a[3])),
          "r"(__float_as_uint(b[0])), "r"(__float_as_uint(b[1])));
}

// int8 m16n8k32 (coarse)
__device__ __forceinline__ void mma_s8(int* c, const uint32_t* a, const uint32_t* b) {
    asm volatile(
        "mma.sync.aligned.m16n8k32.row.col.s32.s8.s8.s32 "
        "{%0,%1,%2,%3}, {%4,%5,%6,%7}, {%8,%9}, {%0,%1,%2,%3};"
        : "+r"(c[0]), "+r"(c[1]), "+r"(c[2]), "+r"(c[3])
        : "r"(a[0]), "r"(a[1]), "r"(a[2]), "r"(a[3]),
          "r"(b[0]), "r"(b[1]));
}

__device__ __forceinline__ int dperm(int c) {
    int inner = c & 7;
    return (c & ~7) + ((inner & 3) * 2) + (inner >> 2);
}
__device__ __forceinline__ int invperm(int p) {
    int inner = p & 7;
    return (p & ~7) + ((inner & 1) * 4) + (inner >> 1);
}

__device__ __forceinline__ uint32_t pack4(int d0, int d1, int d2, int d3) {
    return (uint32_t)(d0 & 0xFF) | ((uint32_t)(d1 & 0xFF) << 8) |
           ((uint32_t)(d2 & 0xFF) << 16) | ((uint32_t)(d3 & 0xFF) << 24);
}

// ============================================================================
// init
// ============================================================================
__global__ void init_kernel(const float* __restrict__ cluster_size,
                            const float* __restrict__ embed_avg,
                            float* __restrict__ cs_out,
                            float* __restrict__ avg_out) {
    int t = blockIdx.x * blockDim.x + threadIdx.x;
    if (t < NK) cs_out[t] = 0.99f * cluster_size[t];
    if (t < NK * DD) avg_out[t] = 0.99f * embed_avg[t];
    if (t == 0) { g_maxB2Bits = 0; g_flagCnt = 0; }
}

// ============================================================================
// Row L2-normalize (final new_embedding). One warp per row.
// ============================================================================
__global__ void norm_rows_kernel(const float* __restrict__ in,
                                 float* __restrict__ out, int nrows) {
    int warp = (blockIdx.x * blockDim.x + threadIdx.x) >> 5;
    int lane = threadIdx.x & 31;
    if (warp >= nrows) return;
    const float4* ip = reinterpret_cast<const float4*>(in + (size_t)warp * DD);
    float4 v0 = ip[lane];
    float4 v1 = ip[lane + 32];
    float s = v0.x*v0.x + v0.y*v0.y + v0.z*v0.z + v0.w*v0.w
            + v1.x*v1.x + v1.y*v1.y + v1.z*v1.z + v1.w*v1.w;
    #pragma unroll
    for (int off = 16; off > 0; off >>= 1) s += __shfl_xor_sync(0xFFFFFFFFu, s, off);
    float nrm = fmaxf(sqrtf(s), 1e-12f);
    float4 o0, o1;
    o0.x = v0.x/nrm; o0.y = v0.y/nrm; o0.z = v0.z/nrm; o0.w = v0.w/nrm;
    o1.x = v1.x/nrm; o1.y = v1.y/nrm; o1.z = v1.z/nrm; o1.w = v1.w/nrm;
    float4* op = reinterpret_cast<float4*>(out + (size_t)warp * DD);
    op[lane] = o0; op[lane + 32] = o1;
}

// ============================================================================
// normalize codebook rows + exact tf32 split (permuted).
// ============================================================================
__global__ void norm_split_embed(const float* __restrict__ in) {
    int warp = (blockIdx.x * blockDim.x + threadIdx.x) >> 5;
    int lane = threadIdx.x & 31;
    if (warp >= NK) return;
    const float4* ip = reinterpret_cast<const float4*>(in + (size_t)warp * DD);
    float4 v0 = ip[lane];
    float4 v1 = ip[lane + 32];
    float s = v0.x*v0.x + v0.y*v0.y + v0.z*v0.z + v0.w*v0.w
            + v1.x*v1.x + v1.y*v1.y + v1.z*v1.z + v1.w*v1.w;
    #pragma unroll
    for (int off = 16; off > 0; off >>= 1) s += __shfl_xor_sync(0xFFFFFFFFu, s, off);
    float inv = 1.0f / fmaxf(sqrtf(s), 1e-12f);
    float vv[8] = {v0.x, v0.y, v0.z, v0.w, v1.x, v1.y, v1.z, v1.w};
    #pragma unroll
    for (int i = 0; i < 8; i++) {
        int c = (i < 4) ? (lane * 4 + i) : (128 + lane * 4 + (i - 4));
        float v = vv[i] * inv;
        float h = tf32_rna(v);
        float l = v - h;
        int dp = dperm(c);
        g_Bhi[(size_t)warp * DD + dp] = h;
        g_Blo[(size_t)warp * DD + dp] = l;
    }
}

// ============================================================================
// Transpose z -> token-major, exact tf32 split (permuted).
// ============================================================================
__global__ void transpose_split(const float* __restrict__ z) {
    __shared__ float t[32][33];
    int tx = threadIdx.x, ty = threadIdx.y;
    int hw0 = blockIdx.x * 32, d0 = blockIdx.y * 32, b = blockIdx.z;
    const float* zb = z + (size_t)b * DD * HWSZ;
    #pragma unroll
    for (int i = 0; i < 4; i++) {
        int d = d0 + ty + i * 8;
        t[ty + i * 8][tx] = zb[(size_t)d * HWSZ + hw0 + tx];
    }
    __syncthreads();
    int dp = d0 + dperm(tx);
    #pragma unroll
    for (int i = 0; i < 4; i++) {
        int hwl = ty + i * 8;
        int n = b * HWSZ + hw0 + hwl;
        float v = t[tx][hwl];
        float h = tf32_rna(v);
        float l = v - h;
        g_Ahi[(size_t)n * DD + dp] = h;
        g_Alo[(size_t)n * DD + dp] = l;
    }
}

// ============================================================================
// quantA: warp per token. a = Ahi+Alo (exact). Per-token max -> sA, 2-digit
// int8 quantization (physical/permuted order), norms ||a||, ||a2||.
// ============================================================================
__global__ void quantA_kernel() {
    int warp = (blockIdx.x * blockDim.x + threadIdx.x) >> 5;
    int lane = threadIdx.x & 31;
    if (warp >= NTOK) return;
    const float4* hp = reinterpret_cast<const float4*>(g_Ahi + (size_t)warp * DD);
    const float4* lp = reinterpret_cast<const float4*>(g_Alo + (size_t)warp * DD);
    float4 h0 = hp[lane], h1 = hp[lane + 32];
    float4 l0 = lp[lane], l1 = lp[lane + 32];
    float a[8] = {h0.x + l0.x, h0.y + l0.y, h0.z + l0.z, h0.w + l0.w,
                  h1.x + l1.x, h1.y + l1.y, h1.z + l1.z, h1.w + l1.w};
    float mx = 0.0f, s2 = 0.0f;
    #pragma unroll
    for (int i = 0; i < 8; i++) { mx = fmaxf(mx, fabsf(a[i])); s2 += a[i] * a[i]; }
    #pragma unroll
    for (int off = 16; off > 0; off >>= 1) {
        mx = fmaxf(mx, __shfl_xor_sync(0xFFFFFFFFu, mx, off));
        s2 += __shfl_xor_sync(0xFFFFFFFFu, s2, off);
    }
    float sA = SBQ / fmaxf(mx, 1e-30f);
    int d1[8], d2[8];
    float a22 = 0.0f;
    #pragma unroll
    for (int i = 0; i < 8; i++) {
        float qa = rintf(a[i] * sA);
        float f1 = rintf(qa * (1.0f / 128.0f));
        float f2 = qa - 128.0f * f1;
        d1[i] = (int)f1; d2[i] = (int)f2;
        a22 += f2 * f2;
    }
    #pragma unroll
    for (int off = 16; off > 0; off >>= 1) a22 += __shfl_xor_sync(0xFFFFFFFFu, a22, off);
    uint32_t* p1 = (uint32_t*)(g_A1 + (size_t)warp * DD);
    uint32_t* p2 = (uint32_t*)(g_A2 + (size_t)warp * DD);
    p1[lane]      = pack4(d1[0], d1[1], d1[2], d1[3]);
    p1[lane + 32] = pack4(d1[4], d1[5], d1[6], d1[7]);
    p2[lane]      = pack4(d2[0], d2[1], d2[2], d2[3]);
    p2[lane + 32] = pack4(d2[4], d2[5], d2[6], d2[7]);
    if (lane == 0) {
        g_sA[warp] = sA;
        g_nA[warp] = sqrtf(s2);
        g_nA2[warp] = sqrtf(a22);
    }
}

// ============================================================================
// quantB: warp per code. b = Bhi+Blo (exact normalized row). sB global.
// ============================================================================
__global__ void quantB_kernel() {
    int warp = (blockIdx.x * blockDim.x + threadIdx.x) >> 5;
    int lane = threadIdx.x & 31;
    if (warp >= NK) return;
    const float4* hp = reinterpret_cast<const float4*>(g_Bhi + (size_t)warp * DD);
    const float4* lp = reinterpret_cast<const float4*>(g_Blo + (size_t)warp * DD);
    float4 h0 = hp[lane], h1 = hp[lane + 32];
    float4 l0 = lp[lane], l1 = lp[lane + 32];
    float b[8] = {h0.x + l0.x, h0.y + l0.y, h0.z + l0.z, h0.w + l0.w,
                  h1.x + l1.x, h1.y + l1.y, h1.z + l1.z, h1.w + l1.w};
    int d1[8], d2[8];
    float b22 = 0.0f;
    #pragma unroll
    for (int i = 0; i < 8; i++) {
        float qb = rintf(b[i] * SBQ);
        qb = fminf(fmaxf(qb, -16300.0f), 16300.0f);
        float f1 = rintf(qb * (1.0f / 128.0f));
        float f2 = qb - 128.0f * f1;
        d1[i] = (int)f1; d2[i] = (int)f2;
        b22 += f2 * f2;
    }
    #pragma unroll
    for (int off = 16; off > 0; off >>= 1) b22 += __shfl_xor_sync(0xFFFFFFFFu, b22, off);
    uint32_t* p1 = (uint32_t*)(g_B1 + (size_t)warp * DD);
    uint32_t* p2 = (uint32_t*)(g_B2 + (size_t)warp * DD);
    p1[lane]      = pack4(d1[0], d1[1], d1[2], d1[3]);
    p1[lane + 32] = pack4(d1[4], d1[5], d1[6], d1[7]);
    p2[lane]      = pack4(d2[0], d2[1], d2[2], d2[3]);
    p2[lane + 32] = pack4(d2[4], d2[5], d2[6], d2[7]);
    if (lane == 0) atomicMax(&g_maxB2Bits, __float_as_int(sqrtf(b22)));
}

// ============================================================================
// INT8 coarse GEMM: CTA = 32 tokens x 1024 codes. 128 thr, 4 warps (n-bands),
// warptile 32x32, d-chunk 32 (one k32 mma step), 3 digit-passes per step.
// V = 16384*P11 + 128*(P12+P21); exact s32 accumulate; float-convert epilogue
// reuses the proven tree-max/second-best code. 3-stage cp.async, 4 CTAs/SM.
// ============================================================================
#define ISTG   10240           // A1 1K + A2 1K + B1 4K + B2 4K
#define IGSM   (3*ISTG)        // 30720

__global__ __launch_bounds__(128, 4) void coarse_int8() {
    extern __shared__ float smf[];
    uint32_t* smw = (uint32_t*)smf;
    const uint32_t sbase = smem_to_u32(smf);
    const int tid  = threadIdx.x;
    const int wc   = tid >> 5;
    const int lane = tid & 31;
    const int g  = lane >> 2;
    const int tg = lane & 3;

    const int tile    = blockIdx.x >> 3;
    const int slice   = blockIdx.x & 7;
    const int rowBase = tile * 32;
    const int kBase   = slice * KSLICE;

    int acc11[2][4][4], accmid[2][4][4];
    #pragma unroll
    for (int mt = 0; mt < 2; mt++)
        #pragma unroll
        for (int nt = 0; nt < 4; nt++)
            #pragma unroll
            for (int q = 0; q < 4; q++) { acc11[mt][nt][q] = 0; accmid[mt][nt][q] = 0; }

    float bestV[4], secV[4];
    int   bestI[4];
    #pragma unroll
    for (int s = 0; s < 4; s++) {
        bestV[s] = -INFINITY; secV[s] = -INFINITY; bestI[s] = 0x7fffffff;
    }

    // loader: 5 cp.async per thread
    const int aT = tid >> 6;
    const int ar = (tid >> 1) & 31;
    const int hb = tid & 1;
    const int br = (tid >> 1) & 63;
    const char* srcA  = (aT ? g_A2 : g_A1) + ((size_t)(rowBase + ar) * DD + hb * 16);
    const char* srcB1 = g_B1 + ((size_t)(kBase + br) * DD + hb * 16);
    const char* srcB2 = g_B2 + ((size_t)(kBase + br) * DD + hb * 16);
    const uint32_t dstA  = (uint32_t)(aT * 1024 + ar * 32 + hb * 16);
    const uint32_t dstB1 = (uint32_t)(2048 + br * 32 + hb * 16);
    const uint32_t dstB2 = (uint32_t)(6144 + br * 32 + hb * 16);
    int ldj = 0;
    auto load = [&](uint32_t sb) {
        cpasync16(sb + dstA, srcA);
        cpasync16(sb + dstB1, srcB1);
        cpasync16(sb + dstB1 + 2048, srcB1 + 64 * DD);
        cpasync16(sb + dstB2, srcB2);
        cpasync16(sb + dstB2 + 2048, srcB2 + 64 * DD);
        CPASYNC_COMMIT();
        int wrap = ((ldj & 7) == 7);
        ldj++;
        int dA = wrap ? (32 - 256) : 32;
        int dB = wrap ? (32 - 256 + 128 * DD) : 32;
        srcA += dA; srcB1 += dB; srcB2 += dB;
    };

    const uint32_t stB0 = sbase, stB1s = sbase + ISTG, stB2s = sbase + 2 * ISTG;
    load(stB0); load(stB1s);
    CPASYNC_WAIT(1);
    __syncthreads();

    int stg = 0;
    uint32_t stNext = stB2s;
    for (int it = 0; it < 64; it++) {
        if (it < 62) load(stNext);

        const uint32_t* W = smw + stg * (ISTG / 4);
        // fragments
        uint32_t a1f[2][4], a2f[2][4], b1f[4][2], b2f[4][2];
        #pragma unroll
        for (int mt = 0; mt < 2; mt++) {
            int rb = (mt * 16 + g) * 8 + tg;
            a1f[mt][0] = W[rb];           a1f[mt][1] = W[rb + 64];
            a1f[mt][2] = W[rb + 4];       a1f[mt][3] = W[rb + 68];
            a2f[mt][0] = W[256 + rb];     a2f[mt][1] = W[256 + rb + 64];
            a2f[mt][2] = W[256 + rb + 4]; a2f[mt][3] = W[256 + rb + 68];
        }
        #pragma unroll
        for (int nt = 0; nt < 4; nt++) {
            int rb = (wc * 32 + nt * 8 + g) * 8 + tg;
            b1f[nt][0] = W[512 + rb];  b1f[nt][1] = W[512 + rb + 4];
            b2f[nt][0] = W[1536 + rb]; b2f[nt][1] = W[1536 + rb + 4];
        }
        #pragma unroll
        for (int mt = 0; mt < 2; mt++)
            #pragma unroll
            for (int nt = 0; nt < 4; nt++) {
                mma_s8(acc11[mt][nt],  a1f[mt], b1f[nt]);
                mma_s8(accmid[mt][nt], a1f[mt], b2f[nt]);
                mma_s8(accmid[mt][nt], a2f[mt], b1f[nt]);
            }

        if ((it & 7) == 7) {
            int colBase = kBase + (it >> 3) * 128 + wc * 32;
            #pragma unroll
            for (int mt = 0; mt < 2; mt++)
                #pragma unroll
                for (int half = 0; half < 2; half++) {
                    int slot = mt * 2 + half;
                    float v[8];
                    #pragma unroll
                    for (int nt = 0; nt < 4; nt++)
                        #pragma unroll
                        for (int j = 0; j < 2; j++) {
                            int q = half * 2 + j;
                            v[nt * 2 + j] = fmaf(16384.0f, (float)acc11[mt][nt][q],
                                                 128.0f * (float)accmid[mt][nt][q]);
                        }
                    float m01 = fmaxf(v[0], v[1]), m23 = fmaxf(v[2], v[3]);
                    float m45 = fmaxf(v[4], v[5]), m67 = fmaxf(v[6], v[7]);
                    float m1  = fmaxf(fmaxf(m01, m23), fmaxf(m45, m67));
                    if (m1 > bestV[slot]) {
                        secV[slot] = fmaxf(secV[slot], bestV[slot]);
                        int bi = 0x7fffffff;
                        #pragma unroll
                        for (int q = 0; q < 8; q++)
                            if (v[q] == m1) bi = min(bi, colBase + (q >> 1) * 8 + tg * 2 + (q & 1));
                        float m2 = -INFINITY;
                        #pragma unroll
                        for (int q = 0; q < 8; q++) {
                            int cq = colBase + (q >> 1) * 8 + tg * 2 + (q & 1);
                            m2 = fmaxf(m2, (cq == bi) ? -INFINITY : v[q]);
                        }
                        bestV[slot] = m1;
                        bestI[slot] = bi;
                        secV[slot]  = fmaxf(secV[slot], m2);
                    } else {
                        secV[slot] = fmaxf(secV[slot], m1);
                    }
                }
            #pragma unroll
            for (int mt = 0; mt < 2; mt++)
                #pragma unroll
                for (int nt = 0; nt < 4; nt++)
                    #pragma unroll
                    for (int q = 0; q < 4; q++) { acc11[mt][nt][q] = 0; accmid[mt][nt][q] = 0; }
        }

        if (it < 62) CPASYNC_WAIT(1);
        else         CPASYNC_WAIT(0);
        __syncthreads();

        stg++; if (stg == 3) stg = 0;
        stNext += ISTG; if (stNext > stB2s) stNext = stB0;
    }

    // cross-thread merge: 16 contributors (wc x tg) per row, 32 rows
    float* sv1 = smf;
    int*   si1 = (int*)(smf + 512);
    float* sv2 = smf + 1024;
    #pragma unroll
    for (int slot = 0; slot < 4; slot++) {
        int row = (slot >> 1) * 16 + (slot & 1) * 8 + g;
        int ent = row * 16 + wc * 4 + tg;
        sv1[ent] = bestV[slot];
        si1[ent] = bestI[slot];
        sv2[ent] = secV[slot];
    }
    __syncthreads();
    if (tid < 32) {
        float V1 = -INFINITY, V2 = -INFINITY;
        int I1 = 0x7fffffff;
        #pragma unroll
        for (int t = 0; t < 16; t++) {
            float v1 = sv1[tid * 16 + t];
            int   i1 = si1[tid * 16 + t];
            float v2 = sv2[tid * 16 + t];
            if (v1 > V1 || (v1 == V1 && i1 < I1)) {
                V2 = fmaxf(fmaxf(V2, V1), v2);
                V1 = v1; I1 = i1;
            } else {
                V2 = fmaxf(V2, v1);
            }
        }
        size_t e = (size_t)blockIdx.x * 32 + tid;
        g_pv[e] = make_float2(V1, V2);
        g_pi[e] = I1;
    }
}

// ============================================================================
// Merge slices + rigorous INT8 margin test; flag uncertain tokens.
// ============================================================================
__global__ void merge_kernel() {
    int n = blockIdx.x * blockDim.x + threadIdx.x;
    if (n >= NTOK) return;
    int tile = n >> 5, row = n & 31;
    float V1 = -INFINITY, V2 = -INFINITY;
    int I1 = 0x7fffffff;
    #pragma unroll
    for (int s = 0; s < NSLICE; s++) {
        size_t e = ((size_t)(tile * NSLICE + s)) * 32 + row;
        float2 v = g_pv[e];
        int   i1 = g_pi[e];
        if (v.x > V1 || (v.x == V1 && i1 < I1)) {
            V2 = fmaxf(fmaxf(V2, V1), v.y);
            V1 = v.x; I1 = i1;
        } else {
            V2 = fmaxf(V2, v.x);
        }
    }
    float maxB2 = __int_as_float(g_maxB2Bits);
    float sA = g_sA[n];
    // quantized-unit margin: dropped a2*b2 term + quantization + conversion
    float thr = 2.0f * (g_nA2[n] * maxB2 + g_nA[n] * 8.0f * sA
                        + 8.0008f * SBQ + 64.0f)
              + 2.5e-7f * (fabsf(V1) + fabsf(V2)) + 64.0f;
    if (V1 - V2 >= thr) {
        g_idx[n] = I1;
    } else {
        int s = atomicAdd(&g_flagCnt, 1);
        g_flagTok[s] = n;
        g_idx[n] = I1;
    }
}

// ============================================================================
// 3xTF32 tensor-core rescore: 16 K-slices of 512 codes (R15-proven).
// ============================================================================
#define CW3    24
#define RABUF  6144
#define RBBUF  12288
#define RBOFF  (2*RABUF)
#define RSTG   (2*RABUF + 2*RBBUF)
#define RGSM   (2*RSTG)

__global__ __launch_bounds__(128, 2) void rescore_mma() {
    extern __shared__ float sm[];
    const uint32_t sbase = smem_to_u32(sm);
    __shared__ int toks[64];
    int count = g_flagCnt;
    const int tile  = blockIdx.x >> 4;
    const int slice = blockIdx.x & 15;
    const int base  = tile * 64;
    if (base >= count) return;
    const int tid  = threadIdx.x;
    const int wc   = tid >> 5;
    const int lane = tid & 31;
    const int g  = lane >> 2;
    const int tg = lane & 3;
    const int kBase = slice * RKS;

    if (tid < 64) toks[tid] = (base + tid < count) ? g_flagTok[base + tid] : g_flagTok[0];
    __syncthreads();

    const ptrdiff_t ALO = g_Alo - g_Ahi;
    const ptrdiff_t BLO = g_Blo - g_Bhi;

    const int rA = tid >> 2;
    const int cA = tid & 3;
    const float* pA[2];
    const float* pB[4];
    uint32_t offA[2], offB[4];
    #pragma unroll
    for (int j = 0; j < 2; j++) {
        pA[j]   = g_Ahi + ((size_t)toks[rA + 32 * j] * DD + cA * 4);
        offA[j] = (uint32_t)((rA + 32 * j) * 96 + cA * 16);
    }
    #pragma unroll
    for (int j = 0; j < 4; j++) {
        pB[j]   = g_Bhi + ((size_t)(kBase + rA + 32 * j) * DD + cA * 4);
        offB[j] = (uint32_t)(RBOFF + (rA + 32 * j) * 96 + cA * 16);
    }
    int ldj = 0;
    auto load = [&](uint32_t sb) {
        #pragma unroll
        for (int j = 0; j < 2; j++) {
            cpasync16(sb + offA[j],         pA[j]);
            cpasync16(sb + offA[j] + RABUF, pA[j] + ALO);
        }
        #pragma unroll
        for (int j = 0; j < 4; j++) {
            cpasync16(sb + offB[j],         pB[j]);
            cpasync16(sb + offB[j] + RBBUF, pB[j] + BLO);
        }
        CPASYNC_COMMIT();
        int wrap = ((ldj & 15) == 15);
        ldj++;
        int dA = wrap ? (16 - 256) : 16;
        int dB = wrap ? (16 - 256 + 128 * DD) : 16;
        pA[0] += dA; pA[1] += dA;
        #pragma unroll
        for (int j = 0; j < 4; j++) pB[j] += dB;
    };

    float acc[4][4][4];
    #pragma unroll
    for (int mt = 0; mt < 4; mt++)
        #pragma unroll
        for (int nt = 0; nt < 4; nt++)
            #pragma unroll
            for (int q = 0; q < 4; q++) acc[mt][nt][q] = 0.0f;

    float bestV[8];
    int   bestI[8];
    #pragma unroll
    for (int s = 0; s < 8; s++) { bestV[s] = -INFINITY; bestI[s] = 0x7fffffff; }

    load(sbase);
    CPASYNC_WAIT(0);
    __syncthreads();

    for (int it = 0; it < 64; it++) {
        int stg = it & 1;
        if (it < 63) load(sbase + ((it + 1) & 1) * RSTG);

        const float* Ah = sm + stg * (RSTG / 4);
        const float* Al = Ah + (RABUF / 4);
        const float* Bh = Ah + (RBOFF / 4);
        const float* Bl = Bh + (RBBUF / 4);

        #pragma unroll
        for (int ks = 0; ks < 2; ks++) {
            int kp = ks * 8 + 2 * tg;
            float2 ah[4][2], al[4][2], bh[4], bl[4];
            #pragma unroll
            for (int mt = 0; mt < 4; mt++) {
                int ro = (mt * 16 + g) * CW3 + kp;
                ah[mt][0] = *(const float2*)(Ah + ro);
                ah[mt][1] = *(const float2*)(Ah + ro + 8 * CW3);
                al[mt][0] = *(const float2*)(Al + ro);
                al[mt][1] = *(const float2*)(Al + ro + 8 * CW3);
            }
            #pragma unroll
            for (int nt = 0; nt < 4; nt++) {
                int co = (wc * 32 + nt * 8 + g) * CW3 + kp;
                bh[nt] = *(const float2*)(Bh + co);
                bl[nt] = *(const float2*)(Bl + co);
            }
            #pragma unroll
            for (int mt = 0; mt < 4; mt++)
                #pragma unroll
                for (int nt = 0; nt < 4; nt++) {
                    float ahr[4] = {ah[mt][0].x, ah[mt][1].x, ah[mt][0].y, ah[mt][1].y};
                    float alr[4] = {al[mt][0].x, al[mt][1].x, al[mt][0].y, al[mt][1].y};
                    float bhr[2] = {bh[nt].x, bh[nt].y};
                    float blr[2] = {bl[nt].x, bl[nt].y};
                    mma8(acc[mt][nt], ahr, bhr);
                    mma8(acc[mt][nt], ahr, blr);
                    mma8(acc[mt][nt], alr, bhr);
                }
        }

        if ((it & 15) == 15) {
            int colBase = kBase + (it >> 4) * 128 + wc * 32;
            #pragma unroll
            for (int mt = 0; mt < 4; mt++)
                #pragma unroll
                for (int half = 0; half < 2; half++) {
                    int slot = mt * 2 + half;
                    float v[8];
                    #pragma unroll
                    for (int nt = 0; nt < 4; nt++)
                        #pragma unroll
                        for (int j = 0; j < 2; j++)
                            v[nt * 2 + j] = acc[mt][nt][half * 2 + j];
                    float m01 = fmaxf(v[0], v[1]), m23 = fmaxf(v[2], v[3]);
                    float m45 = fmaxf(v[4], v[5]), m67 = fmaxf(v[6], v[7]);
                    float m1  = fmaxf(fmaxf(m01, m23), fmaxf(m45, m67));
                    if (m1 > bestV[slot]) {
                        int bi = 0x7fffffff;
                        #pragma unroll
                        for (int q = 0; q < 8; q++)
                            if (v[q] == m1) bi = min(bi, colBase + (q >> 1) * 8 + tg * 2 + (q & 1));
                        bestV[slot] = m1;
                        bestI[slot] = bi;
                    }
                }
            #pragma unroll
            for (int mt = 0; mt < 4; mt++)
                #pragma unroll
                for (int nt = 0; nt < 4; nt++)
                    #pragma unroll
                    for (int q = 0; q < 4; q++) acc[mt][nt][q] = 0.0f;
        }

        CPASYNC_WAIT(0);
        __syncthreads();
    }

    float* sv = sm;
    int*   si = (int*)(sm + 1024);
    #pragma unroll
    for (int slot = 0; slot < 8; slot++) {
        int row = (slot >> 1) * 16 + (slot & 1) * 8 + g;
        int ent = row * 16 + wc * 4 + tg;
        sv[ent] = bestV[slot];
        si[ent] = bestI[slot];
    }
    __syncthreads();
    if (tid < 64 && base + tid < count) {
        float bv = sv[tid * 16];
        int   bi = si[tid * 16];
        #pragma unroll
        for (int t = 1; t < 16; t++) {
            float v = sv[tid * 16 + t];
            int  id = si[tid * 16 + t];
            if (v > bv || (v == bv && id < bi)) { bv = v; bi = id; }
        }
        g_rv[(size_t)(base + tid) * RSLICE + slice] = bv;
        g_ri[(size_t)(base + tid) * RSLICE + slice] = bi;
    }
}

// ============================================================================
// merge2: fold 16 slice partials for flagged tokens
// ============================================================================
__global__ void merge2_kernel() {
    int slot = blockIdx.x * blockDim.x + threadIdx.x;
    if (slot >= g_flagCnt || slot >= NTOK) return;
    float bv = -INFINITY; int bi = 0x7fffffff;
    #pragma unroll
    for (int s = 0; s < RSLICE; s++) {
        float v = g_rv[(size_t)slot * RSLICE + s];
        int   i = g_ri[(size_t)slot * RSLICE + s];
        if (v > bv || (v == bv && i < bi)) { bv = v; bi = i; }
    }
    g_idx[g_flagTok[slot]] = bi;
}

// ============================================================================
// finishA / finishB (R15-proven)
// ============================================================================
__global__ void finishA_kernel(const float* __restrict__ embedding,
                               float* __restrict__ avg_out,
                               float* __restrict__ cs_out,
                               float* __restrict__ idxf) {
    int warp = (blockIdx.x * blockDim.x + threadIdx.x) >> 5;
    int lane = threadIdx.x & 31;
    if (warp >= NTOK) return;
    int id = __ldg(&g_idx[warp]);
    if (lane == 0) {
        atomicAdd(&cs_out[id], 0.01f);
        idxf[warp] = (float)id;
    }
    const float* hp = g_Ahi + (size_t)warp * DD;
    const float* lp = g_Alo + (size_t)warp * DD;
    const float* er = embedding + (size_t)id * DD;
    float* avr = avg_out + (size_t)id * DD;
    float* zqr = g_zqT + (size_t)warp * DD;
    #pragma unroll
    for (int half = 0; half < 2; half++) {
        int pb = half * 128 + lane * 4;
        float4 h4 = *(const float4*)(hp + pb);
        float4 l4 = *(const float4*)(lp + pb);
        float hv[4] = {h4.x, h4.y, h4.z, h4.w};
        float lv[4] = {l4.x, l4.y, l4.z, l4.w};
        #pragma unroll
        for (int j = 0; j < 4; j++) {
            int p = pb + j;
            int c = invperm(p);
            float v = hv[j] + lv[j];
            zqr[c] = __ldg(er + c);
            atomicAdd(avr + c, 0.01f * v);
        }
    }
}

__global__ void finishB_kernel(const float* __restrict__ z,
                               float* __restrict__ zst,
                               float* __restrict__ zq) {
    __shared__ float tq[32][33];
    int tx = threadIdx.x, ty = threadIdx.y;
    int hw0 = blockIdx.x * 32, d0 = blockIdx.y * 32, b = blockIdx.z;
    #pragma unroll
    for (int i = 0; i < 4; i++) {
        int hwl = ty + i * 8;
        size_t o = ((size_t)(b * HWSZ + hw0 + hwl)) * DD + d0 + tx;
        tq[hwl][tx] = g_zqT[o];
    }
    __syncthreads();
    const float* zb = z + (size_t)b * DD * HWSZ;
    float* zqb  = zq  + (size_t)b * DD * HWSZ;
    float* zstb = zst + (size_t)b * DD * HWSZ;
    #pragma unroll
    for (int i = 0; i < 4; i++) {
        int dl = ty + i * 8;
        size_t o = (size_t)(d0 + dl) * HWSZ + hw0 + tx;
        float e  = tq[tx][dl];
        float zv = zb[o];
        zqb[o]  = e;
        zstb[o] = zv + (e - zv);
    }
}

// ============================================================================
extern "C" void kernel_launch(void* const* d_in, const int* in_sizes, int n_in,
                              void* d_out, int out_size) {
    const float* z            = (const float*)d_in[0];
    const float* embedding    = (const float*)d_in[1];
    const float* cluster_size = (const float*)d_in[2];
    const float* embed_avg    = (const float*)d_in[3];

    float* out   = (float*)d_out;
    float* zst_o = out + OFF_ZST;
    float* idx_o = out + OFF_IDX;
    float* zq_o  = out + OFF_ZQ;
    float* emb_o = out + OFF_EMB;
    float* cs_o  = out + OFF_CS;
    float* avg_o = out + OFF_AVG;

    init_kernel<<<(NK * DD + 255) / 256, 256>>>(cluster_size, embed_avg, cs_o, avg_o);

    norm_split_embed<<<NK / 8, 256>>>(embedding);
    transpose_split<<<dim3(HWSZ / 32, DD / 32, 8), dim3(32, 8)>>>(z);
    quantA_kernel<<<NTOK / 8, 256>>>();
    quantB_kernel<<<NK / 8, 256>>>();

    static bool attr_set = false;
    if (!attr_set) {
        cudaFuncSetAttribute(coarse_int8,
                             cudaFuncAttributeMaxDynamicSharedMemorySize, IGSM);
        cudaFuncSetAttribute(rescore_mma,
                             cudaFuncAttributeMaxDynamicSharedMemorySize, RGSM);
        attr_set = true;
    }
    coarse_int8<<<NTILE32 * NSLICE, 128, IGSM>>>();

    merge_kernel<<<NTOK / 256, 256>>>();

    rescore_mma<<<(NTOK / 64) * RSLICE, 128, RGSM>>>();

    merge2_kernel<<<NTOK / 256, 256>>>();

    finishA_kernel<<<NTOK / 8, 256>>>(embedding, avg_o, cs_o, idx_o);
    finishB_kernel<<<dim3(HWSZ / 32, DD / 32, 8), dim3(32, 8)>>>(z, zst_o, zq_o);

    norm_rows_kernel<<<NK / 8, 256>>>(avg_o, emb_o, NK);
}